// round 14
// baseline (speedup 1.0000x reference)
#include <cuda_runtime.h>
#include <cuda_fp16.h>
#include <cstdint>

// ---------------------------------------------------------------------------
// Problem constants
//   x: (8, 16, 4, 64, 64) f32      A_IN=16, C_IN=4
//   W: (256, 16, 5, 5)    f32      C_OUT*A_OUT=256
//   b: (1, 1, 8, 32)      f32
//   out: (8, 32, 8, 64, 64) f32
// ---------------------------------------------------------------------------

static __device__ float g_t[32 * 16 * 64 * 64];      // conv input "t" (8 MB)
static __device__ __half g_wA[25 * 256 * 16];        // [pos][o][ic-permuted] fp16
static __device__ float g_conv[32 * 256 * 64 * 64];  // votes fp32 (134 MB)

// ---------------- PTX helpers ----------------------------------------------
__device__ __forceinline__ uint32_t smem_u32(const void* p) {
    uint32_t a;
    asm("{ .reg .u64 t; cvta.to.shared.u64 t, %1; cvt.u32.u64 %0, t; }"
        : "=r"(a) : "l"(p));
    return a;
}
__device__ __forceinline__ void ldm_x4(uint32_t* r, uint32_t addr) {
    asm volatile("ldmatrix.sync.aligned.m8n8.x4.shared.b16 {%0,%1,%2,%3}, [%4];"
                 : "=r"(r[0]), "=r"(r[1]), "=r"(r[2]), "=r"(r[3]) : "r"(addr));
}
__device__ __forceinline__ void mma_fp16(float* c, const uint32_t* a,
                                         uint32_t b0, uint32_t b1) {
    asm volatile(
        "mma.sync.aligned.m16n8k16.row.col.f32.f16.f16.f32 "
        "{%0,%1,%2,%3}, {%4,%5,%6,%7}, {%8,%9}, {%0,%1,%2,%3};"
        : "+f"(c[0]), "+f"(c[1]), "+f"(c[2]), "+f"(c[3])
        : "r"(a[0]), "r"(a[1]), "r"(a[2]), "r"(a[3]), "r"(b0), "r"(b1));
}

// smem: B halo only, 408 rows x 48B pitch (validated conflict-free)
#define B_OFF 0
#define SMEM_BYTES 20480   // 408*48 = 19584, rounded

// ---------------------------------------------------------------------------
// prep_t (smem transpose, validated R9)
// ---------------------------------------------------------------------------
__global__ __launch_bounds__(256) void prep_t_kernel(const float* __restrict__ x) {
    __shared__ float s[16][65];
    const int blk = blockIdx.x;          // 0..2047
    const int h  = blk & 63;
    const int ci = (blk >> 6) & 3;
    const int b  = blk >> 8;
    const int tid = threadIdx.x;

    {
        const int a = tid >> 4, wq = (tid & 15) * 4;
        const float4 v = *(const float4*)(x + (((b * 16 + a) * 4 + ci) << 12)
                                            + (h << 6) + wq);
        s[a][wq]     = v.x;
        s[a][wq + 1] = v.y;
        s[a][wq + 2] = v.z;
        s[a][wq + 3] = v.w;
    }
    __syncthreads();
    {
        float* dst = g_t + (((ci * 8 + b) * 64 + h) << 6) * 16 + tid * 4;
        const int i0 = tid * 4;
        float4 v;
        v.x = s[(i0)     & 15][(i0)     >> 4];
        v.y = s[(i0 + 1) & 15][(i0 + 1) >> 4];
        v.z = s[(i0 + 2) & 15][(i0 + 2) >> 4];
        v.w = s[(i0 + 3) & 15][(i0 + 3) >> 4];
        *(float4*)dst = v;
    }
}

// ---------------------------------------------------------------------------
// prep_wA: fp16 weights, ic u32-pairs permuted for direct LDG.64 A-frags
// (validated R11).
// ---------------------------------------------------------------------------
__global__ void prep_wA_kernel(const float* __restrict__ W) {
    int idx = blockIdx.x * 256 + threadIdx.x;   // 0..102399
    int ic  = idx & 15;
    int o   = (idx >> 4) & 255;
    int pos = idx >> 12;
    float w = W[o * 400 + ic * 25 + pos];
    int p  = ic >> 1;
    int sp = (p < 4) ? (2 * p) : (2 * (p - 4) + 1);
    int store_ic = sp * 2 + (ic & 1);
    g_wA[pos * 4096 + o * 16 + store_ic] = __float2half_rn(w);
}

// ---------------------------------------------------------------------------
// conv: byte-identical to R11 (25 shifted GEMMs, single-pass fp16, fp32 out)
// ---------------------------------------------------------------------------
__global__ __launch_bounds__(256, 2) void conv_mma_kernel() {
    extern __shared__ char dsm[];
    const int pxt = blockIdx.x;
    const int oh  = blockIdx.y;
    const int n   = blockIdx.z;
    const int tid = threadIdx.x;
    const int lane = tid & 31, wid = tid >> 5;
    const int wr = wid >> 2, wc = wid & 3;
    const int lh = wc >> 1, wwbase = (wc & 1) * 32;

    const uint32_t sb = smem_u32(dsm);
    const int hbase = pxt * 2;

    const int bRow = (lane & 7) + (lane >> 4) * 8;
    const int bCol = ((lane >> 3) & 1) * 8;
    const uint32_t bStat = (uint32_t)(bRow * 48 + bCol * 2);

    {
        const float* tn = g_t + n * 65536;
#pragma unroll
        for (int base = tid; base < 408; base += 256) {
            int r = base / 68, c = base % 68;
            int y = hbase + r - 2;
            int x = c - 2;
            bool ok = ((unsigned)y < 64u) && ((unsigned)x < 64u);
            __half* row = (__half*)(dsm + B_OFF + base * 48);
            const float* src = tn + y * 64 + x;
#pragma unroll
            for (int ic = 0; ic < 16; ic++) {
                float v = ok ? __ldg(src + ic * 4096) : 0.f;
                row[ic] = __float2half_rn(v);
            }
        }
    }
    __syncthreads();

    const uint2* gA2 = (const uint2*)g_wA;
    const int aBase = (oh * 128 + wr * 64 + (lane >> 2)) * 4 + (lane & 3);

    float acc[4][4][4];
#pragma unroll
    for (int mf = 0; mf < 4; mf++)
#pragma unroll
        for (int nf = 0; nf < 4; nf++)
#pragma unroll
            for (int q = 0; q < 4; q++) acc[mf][nf][q] = 0.f;

#pragma unroll 1
    for (int kh = 0; kh < 5; kh++) {
        const uint32_t Brow = sb + B_OFF
            + (uint32_t)(((lh + kh) * 68 + wwbase) * 48) + bStat;
#pragma unroll
        for (int kw = 0; kw < 5; kw++) {
            const int pos = kh * 5 + kw;
            const uint2* ap = gA2 + pos * 1024 + aBase;

            uint32_t a4[4][4];
#pragma unroll
            for (int mf = 0; mf < 4; mf++) {
                uint2 lo = __ldg(ap + mf * 64);
                uint2 hi = __ldg(ap + mf * 64 + 32);
                a4[mf][0] = lo.x;
                a4[mf][2] = lo.y;
                a4[mf][1] = hi.x;
                a4[mf][3] = hi.y;
            }

            uint32_t bh[2][4];
            ldm_x4(bh[0], Brow + kw * 48);
            ldm_x4(bh[1], Brow + (16 + kw) * 48);

#pragma unroll
            for (int mf = 0; mf < 4; mf++) {
                mma_fp16(acc[mf][0], a4[mf], bh[0][0], bh[0][1]);
                mma_fp16(acc[mf][1], a4[mf], bh[0][2], bh[0][3]);
                mma_fp16(acc[mf][2], a4[mf], bh[1][0], bh[1][1]);
                mma_fp16(acc[mf][3], a4[mf], bh[1][2], bh[1][3]);
            }
        }
    }

    const int g2  = lane >> 2, t4 = lane & 3;
    float* outn = g_conv + n * 1048576;
    const int obase  = oh * 128 + wr * 64 + g2;
    const int pxbase = pxt * 128 + wc * 32 + 2 * t4;
#pragma unroll
    for (int mf = 0; mf < 4; mf++) {
#pragma unroll
        for (int nf = 0; nf < 4; nf++) {
            float* p0 = outn + (obase + mf * 16) * 4096 + pxbase + nf * 8;
            *(float2*)p0 = make_float2(acc[mf][nf][0], acc[mf][nf][1]);
            *(float2*)(p0 + 8 * 4096) = make_float2(acc[mf][nf][2], acc[mf][nf][3]);
        }
    }
}

// ---------------------------------------------------------------------------
// routing: one warp per pixel, lane = atom (math identical to R11).
// v[0..1] in registers; v[2..3] in per-thread smem slots (lane-indexed,
// conflict-free, no sync needed: writer == reader). Frees 16 regs ->
// launch_bounds(256,5) -> 5 blocks/SM -> occ 62.5%.
// ---------------------------------------------------------------------------
__global__ __launch_bounds__(256, 5) void routing_kernel(const float* __restrict__ bias,
                                                         float* __restrict__ out) {
    const unsigned FULL = 0xffffffffu;
    __shared__ float s_bias[256];
    __shared__ float s_v[8][16][32];     // [warp][(i-2)*8+o][lane]
    s_bias[threadIdx.x] = bias[threadIdx.x];
    __syncthreads();

    int gwarp = (blockIdx.x * 256 + threadIdx.x) >> 5;
    int lane  = threadIdx.x & 31;
    int wloc  = (threadIdx.x >> 5) & 7;
    int b  = gwarp >> 12;
    int hw = gwarp & 4095;

    const float* vb = g_conv + b * 4194304 + hw * 256 + lane;
    float v[2][8];
#pragma unroll
    for (int i = 0; i < 2; i++)
#pragma unroll
        for (int o = 0; o < 8; o++)
            v[i][o] = __ldg(vb + i * 1048576 + o * 32);
#pragma unroll
    for (int i = 2; i < 4; i++)
#pragma unroll
        for (int o = 0; o < 8; o++)
            s_v[wloc][(i - 2) * 8 + o][lane] = __ldg(vb + i * 1048576 + o * 32);

    float logit = 0.f;
    float act[8];

#pragma unroll
    for (int it = 0; it < 3; it++) {
        float pre[8];
        if (it == 0) {
#pragma unroll
            for (int o = 0; o < 8; o++) {
                float p = s_bias[o * 32 + lane];
#pragma unroll
                for (int i = 0; i < 2; i++) p = fmaf(0.125f, v[i][o], p);
#pragma unroll
                for (int i = 2; i < 4; i++)
                    p = fmaf(0.125f, s_v[wloc][(i - 2) * 8 + o][lane], p);
                pre[o] = p;
            }
        } else {
            float m = logit;
            m = fmaxf(m, __shfl_xor_sync(FULL, m, 1));
            m = fmaxf(m, __shfl_xor_sync(FULL, m, 2));
            m = fmaxf(m, __shfl_xor_sync(FULL, m, 4));
            float e = __expf(logit - m);
            float ssum = e;
            ssum += __shfl_xor_sync(FULL, ssum, 1);
            ssum += __shfl_xor_sync(FULL, ssum, 2);
            ssum += __shfl_xor_sync(FULL, ssum, 4);
            float route = e / ssum;
#pragma unroll
            for (int o = 0; o < 8; o++) {
                float p = s_bias[o * 32 + lane];
#pragma unroll
                for (int i = 0; i < 2; i++) {
                    float r = __shfl_sync(FULL, route, i * 8 + o);
                    p = fmaf(r, v[i][o], p);
                }
#pragma unroll
                for (int i = 2; i < 4; i++) {
                    float r = __shfl_sync(FULL, route, i * 8 + o);
                    p = fmaf(r, s_v[wloc][(i - 2) * 8 + o][lane], p);
                }
                pre[o] = p;
            }
        }

        // squash: transpose-reduce (validated R5/R6)
        {
            float g8[8];
#pragma unroll
            for (int o = 0; o < 8; o++) g8[o] = pre[o] * pre[o];
            {
                bool up = (lane & 16) != 0;
#pragma unroll
                for (int k = 0; k < 4; k++) {
                    float send = up ? g8[k] : g8[k + 4];
                    float keep = up ? g8[k + 4] : g8[k];
                    g8[k] = keep + __shfl_xor_sync(FULL, send, 16);
                }
            }
            {
                bool up = (lane & 8) != 0;
#pragma unroll
                for (int k = 0; k < 2; k++) {
                    float send = up ? g8[k] : g8[k + 2];
                    float keep = up ? g8[k + 2] : g8[k];
                    g8[k] = keep + __shfl_xor_sync(FULL, send, 8);
                }
            }
            {
                bool up = (lane & 4) != 0;
                float send = up ? g8[0] : g8[1];
                float keep = up ? g8[1] : g8[0];
                g8[0] = keep + __shfl_xor_sync(FULL, send, 4);
            }
            g8[0] += __shfl_xor_sync(FULL, g8[0], 2);
            g8[0] += __shfl_xor_sync(FULL, g8[0], 1);
#pragma unroll
            for (int o = 0; o < 8; o++) {
                float S = __shfl_sync(FULL, g8[0], (o << 2) | (lane & 3));
                float f = S / ((1.f + S) * sqrtf(S + 1e-7f));
                act[o] = pre[o] * f;
            }
        }

        if (it < 2) {
            float g16[16];
            {
                bool up = (lane & 16) != 0;
#pragma unroll
                for (int k = 0; k < 16; k++) {
                    int i = k >> 3, o = k & 7;
                    float pk  = v[i][o] * act[o];
                    float pk2 = s_v[wloc][i * 8 + o][lane] * act[o];
                    float send = up ? pk : pk2;
                    float keep = up ? pk2 : pk;
                    g16[k] = keep + __shfl_xor_sync(FULL, send, 16);
                }
            }
            int len = 16;
#pragma unroll
            for (int m = 8; m >= 1; m >>= 1) {
                int half = len >> 1;
                bool up = (lane & m) != 0;
#pragma unroll
                for (int k = 0; k < 8; k++) {
                    if (k < half) {
                        float send = up ? g16[k] : g16[k + half];
                        float keep = up ? g16[k + half] : g16[k];
                        g16[k] = keep + __shfl_xor_sync(FULL, send, m);
                    }
                }
                len = half;
            }
            logit += g16[0];
        }
    }

    float* ob = out + ((b * 32 + lane) * 8) * 4096 + hw;
#pragma unroll
    for (int o = 0; o < 8; o++)
        ob[o * 4096] = act[o];
}

// ---------------------------------------------------------------------------
extern "C" void kernel_launch(void* const* d_in, const int* in_sizes, int n_in,
                              void* d_out, int out_size) {
    const float* x = (const float*)d_in[0];
    const float* W = (const float*)d_in[1];
    const float* b = (const float*)d_in[2];
    float* out = (float*)d_out;

    cudaFuncSetAttribute(conv_mma_kernel,
                         cudaFuncAttributeMaxDynamicSharedMemorySize, SMEM_BYTES);

    prep_t_kernel<<<2048, 256>>>(x);
    prep_wA_kernel<<<400, 256>>>(W);
    conv_mma_kernel<<<dim3(32, 2, 32), 256, SMEM_BYTES>>>();
    routing_kernel<<<4096, 256>>>(b, out);
}

// round 15
// speedup vs baseline: 1.1612x; 1.1612x over previous
#include <cuda_runtime.h>
#include <cuda_fp16.h>
#include <cstdint>

// ---------------------------------------------------------------------------
// Problem constants
//   x: (8, 16, 4, 64, 64) f32      A_IN=16, C_IN=4
//   W: (256, 16, 5, 5)    f32      C_OUT*A_OUT=256
//   b: (1, 1, 8, 32)      f32
//   out: (8, 32, 8, 64, 64) f32
// ---------------------------------------------------------------------------

static __device__ float g_t[32 * 16 * 64 * 64];      // conv input "t" (8 MB)
static __device__ __half g_wA[25 * 256 * 16];        // [pos][o][ic-permuted] fp16
static __device__ float g_conv[32 * 256 * 64 * 64];  // votes fp32 (134 MB)

// ---------------- PTX helpers ----------------------------------------------
__device__ __forceinline__ uint32_t smem_u32(const void* p) {
    uint32_t a;
    asm("{ .reg .u64 t; cvta.to.shared.u64 t, %1; cvt.u32.u64 %0, t; }"
        : "=r"(a) : "l"(p));
    return a;
}
__device__ __forceinline__ void ldm_x4(uint32_t* r, uint32_t addr) {
    asm volatile("ldmatrix.sync.aligned.m8n8.x4.shared.b16 {%0,%1,%2,%3}, [%4];"
                 : "=r"(r[0]), "=r"(r[1]), "=r"(r[2]), "=r"(r[3]) : "r"(addr));
}
__device__ __forceinline__ void mma_fp16(float* c, const uint32_t* a,
                                         uint32_t b0, uint32_t b1) {
    asm volatile(
        "mma.sync.aligned.m16n8k16.row.col.f32.f16.f16.f32 "
        "{%0,%1,%2,%3}, {%4,%5,%6,%7}, {%8,%9}, {%0,%1,%2,%3};"
        : "+f"(c[0]), "+f"(c[1]), "+f"(c[2]), "+f"(c[3])
        : "r"(a[0]), "r"(a[1]), "r"(a[2]), "r"(a[3]), "r"(b0), "r"(b1));
}

// smem: B halo only, 408 rows x 48B pitch (validated conflict-free)
#define B_OFF 0
#define SMEM_BYTES 20480   // 408*48 = 19584, rounded

// ---------------------------------------------------------------------------
// prep_t (smem transpose, validated R9)
// ---------------------------------------------------------------------------
__global__ __launch_bounds__(256) void prep_t_kernel(const float* __restrict__ x) {
    __shared__ float s[16][65];
    const int blk = blockIdx.x;          // 0..2047
    const int h  = blk & 63;
    const int ci = (blk >> 6) & 3;
    const int b  = blk >> 8;
    const int tid = threadIdx.x;

    {
        const int a = tid >> 4, wq = (tid & 15) * 4;
        const float4 v = *(const float4*)(x + (((b * 16 + a) * 4 + ci) << 12)
                                            + (h << 6) + wq);
        s[a][wq]     = v.x;
        s[a][wq + 1] = v.y;
        s[a][wq + 2] = v.z;
        s[a][wq + 3] = v.w;
    }
    __syncthreads();
    {
        float* dst = g_t + (((ci * 8 + b) * 64 + h) << 6) * 16 + tid * 4;
        const int i0 = tid * 4;
        float4 v;
        v.x = s[(i0)     & 15][(i0)     >> 4];
        v.y = s[(i0 + 1) & 15][(i0 + 1) >> 4];
        v.z = s[(i0 + 2) & 15][(i0 + 2) >> 4];
        v.w = s[(i0 + 3) & 15][(i0 + 3) >> 4];
        *(float4*)dst = v;
    }
}

// ---------------------------------------------------------------------------
// prep_wA: fp16 weights, ic u32-pairs permuted for direct LDG.64 A-frags
// (validated R11).
// ---------------------------------------------------------------------------
__global__ void prep_wA_kernel(const float* __restrict__ W) {
    int idx = blockIdx.x * 256 + threadIdx.x;   // 0..102399
    int ic  = idx & 15;
    int o   = (idx >> 4) & 255;
    int pos = idx >> 12;
    float w = W[o * 400 + ic * 25 + pos];
    int p  = ic >> 1;
    int sp = (p < 4) ? (2 * p) : (2 * (p - 4) + 1);
    int store_ic = sp * 2 + (ic & 1);
    g_wA[pos * 4096 + o * 16 + store_ic] = __float2half_rn(w);
}

// ---------------------------------------------------------------------------
// conv: 25 shifted GEMMs, K=16, single-pass fp16, fp32 accum.
// FULLY UNROLLED position loop with register double-buffered A prefetch:
// pos+1's 8 LDG.64 issue during pos's 16 MMAs -> load latency hidden.
// ---------------------------------------------------------------------------
__global__ __launch_bounds__(256, 2) void conv_mma_kernel() {
    extern __shared__ char dsm[];
    const int pxt = blockIdx.x;
    const int oh  = blockIdx.y;
    const int n   = blockIdx.z;
    const int tid = threadIdx.x;
    const int lane = tid & 31, wid = tid >> 5;
    const int wr = wid >> 2, wc = wid & 3;
    const int lh = wc >> 1, wwbase = (wc & 1) * 32;

    const uint32_t sb = smem_u32(dsm);
    const int hbase = pxt * 2;

    const int bRow = (lane & 7) + (lane >> 4) * 8;
    const int bCol = ((lane >> 3) & 1) * 8;
    const uint32_t bStat = (uint32_t)(bRow * 48 + bCol * 2);

    // ---- B halo fill (once) + single barrier ------------------------------
    {
        const float* tn = g_t + n * 65536;
#pragma unroll
        for (int base = tid; base < 408; base += 256) {
            int r = base / 68, c = base % 68;
            int y = hbase + r - 2;
            int x = c - 2;
            bool ok = ((unsigned)y < 64u) && ((unsigned)x < 64u);
            __half* row = (__half*)(dsm + B_OFF + base * 48);
            const float* src = tn + y * 64 + x;
#pragma unroll
            for (int ic = 0; ic < 16; ic++) {
                float v = ok ? __ldg(src + ic * 4096) : 0.f;
                row[ic] = __float2half_rn(v);
            }
        }
    }
    __syncthreads();

    const uint2* gA2 = (const uint2*)g_wA;
    const int aBase = (oh * 128 + wr * 64 + (lane >> 2)) * 4 + (lane & 3);

    float acc[4][4][4];
#pragma unroll
    for (int mf = 0; mf < 4; mf++)
#pragma unroll
        for (int nf = 0; nf < 4; nf++)
#pragma unroll
            for (int q = 0; q < 4; q++) acc[mf][nf][q] = 0.f;

    // preload pos 0 A-frags
    uint2 nlo[4], nhi[4];
#pragma unroll
    for (int mf = 0; mf < 4; mf++) {
        nlo[mf] = __ldg(gA2 + aBase + mf * 64);
        nhi[mf] = __ldg(gA2 + aBase + mf * 64 + 32);
    }

#pragma unroll
    for (int pos = 0; pos < 25; pos++) {
        const int kh = pos / 5, kw = pos - kh * 5;

        uint32_t a4[4][4];
#pragma unroll
        for (int mf = 0; mf < 4; mf++) {
            a4[mf][0] = nlo[mf].x;
            a4[mf][2] = nlo[mf].y;
            a4[mf][1] = nhi[mf].x;
            a4[mf][3] = nhi[mf].y;
        }

        if (pos < 24) {   // prefetch next position's A-frags during the MMAs
            const uint2* ap = gA2 + (pos + 1) * 1024 + aBase;
#pragma unroll
            for (int mf = 0; mf < 4; mf++) {
                nlo[mf] = __ldg(ap + mf * 64);
                nhi[mf] = __ldg(ap + mf * 64 + 32);
            }
        }

        const uint32_t Bb = sb + B_OFF
            + (uint32_t)(((lh + kh) * 68 + wwbase + kw) * 48) + bStat;
        uint32_t bh[2][4];
        ldm_x4(bh[0], Bb);
        ldm_x4(bh[1], Bb + 16 * 48);

#pragma unroll
        for (int mf = 0; mf < 4; mf++) {
            mma_fp16(acc[mf][0], a4[mf], bh[0][0], bh[0][1]);
            mma_fp16(acc[mf][1], a4[mf], bh[0][2], bh[0][3]);
            mma_fp16(acc[mf][2], a4[mf], bh[1][0], bh[1][1]);
            mma_fp16(acc[mf][3], a4[mf], bh[1][2], bh[1][3]);
        }
    }

    // ---- epilogue: direct float2 stores into flat [n][o][hw] --------------
    const int g2  = lane >> 2, t4 = lane & 3;
    float* outn = g_conv + n * 1048576;
    const int obase  = oh * 128 + wr * 64 + g2;
    const int pxbase = pxt * 128 + wc * 32 + 2 * t4;
#pragma unroll
    for (int mf = 0; mf < 4; mf++) {
#pragma unroll
        for (int nf = 0; nf < 4; nf++) {
            float* p0 = outn + (obase + mf * 16) * 4096 + pxbase + nf * 8;
            *(float2*)p0 = make_float2(acc[mf][nf][0], acc[mf][nf][1]);
            *(float2*)(p0 + 8 * 4096) = make_float2(acc[mf][nf][2], acc[mf][nf][3]);
        }
    }
}

// ---------------------------------------------------------------------------
// routing: one warp per pixel, lane = atom. R11 form; squash factor f computed
// once on the owner lane and broadcast (saves 14 MUFU/iter/lane, bit-identical).
// ---------------------------------------------------------------------------
__global__ __launch_bounds__(256, 4) void routing_kernel(const float* __restrict__ bias,
                                                         float* __restrict__ out) {
    const unsigned FULL = 0xffffffffu;
    __shared__ float s_bias[256];
    s_bias[threadIdx.x] = bias[threadIdx.x];
    __syncthreads();

    int gwarp = (blockIdx.x * 256 + threadIdx.x) >> 5;
    int lane  = threadIdx.x & 31;
    int b  = gwarp >> 12;
    int hw = gwarp & 4095;

    const float* vb = g_conv + b * 4194304 + hw * 256 + lane;
    float v[4][8];
#pragma unroll
    for (int i = 0; i < 4; i++)
#pragma unroll
        for (int o = 0; o < 8; o++)
            v[i][o] = __ldg(vb + i * 1048576 + o * 32);

    float logit = 0.f;
    float act[8];

#pragma unroll
    for (int it = 0; it < 3; it++) {
        float pre[8];
        if (it == 0) {
#pragma unroll
            for (int o = 0; o < 8; o++) {
                float p = s_bias[o * 32 + lane];
#pragma unroll
                for (int i = 0; i < 4; i++) p = fmaf(0.125f, v[i][o], p);
                pre[o] = p;
            }
        } else {
            float m = logit;
            m = fmaxf(m, __shfl_xor_sync(FULL, m, 1));
            m = fmaxf(m, __shfl_xor_sync(FULL, m, 2));
            m = fmaxf(m, __shfl_xor_sync(FULL, m, 4));
            float e = __expf(logit - m);
            float ssum = e;
            ssum += __shfl_xor_sync(FULL, ssum, 1);
            ssum += __shfl_xor_sync(FULL, ssum, 2);
            ssum += __shfl_xor_sync(FULL, ssum, 4);
            float route = e / ssum;
#pragma unroll
            for (int o = 0; o < 8; o++) {
                float p = s_bias[o * 32 + lane];
#pragma unroll
                for (int i = 0; i < 4; i++) {
                    float r = __shfl_sync(FULL, route, i * 8 + o);
                    p = fmaf(r, v[i][o], p);
                }
                pre[o] = p;
            }
        }

        // squash: transpose-reduce; f computed on owner lane, broadcast
        {
            float g8[8];
#pragma unroll
            for (int o = 0; o < 8; o++) g8[o] = pre[o] * pre[o];
            {
                bool up = (lane & 16) != 0;
#pragma unroll
                for (int k = 0; k < 4; k++) {
                    float send = up ? g8[k] : g8[k + 4];
                    float keep = up ? g8[k + 4] : g8[k];
                    g8[k] = keep + __shfl_xor_sync(FULL, send, 16);
                }
            }
            {
                bool up = (lane & 8) != 0;
#pragma unroll
                for (int k = 0; k < 2; k++) {
                    float send = up ? g8[k] : g8[k + 2];
                    float keep = up ? g8[k + 2] : g8[k];
                    g8[k] = keep + __shfl_xor_sync(FULL, send, 8);
                }
            }
            {
                bool up = (lane & 4) != 0;
                float send = up ? g8[0] : g8[1];
                float keep = up ? g8[1] : g8[0];
                g8[0] = keep + __shfl_xor_sync(FULL, send, 4);
            }
            g8[0] += __shfl_xor_sync(FULL, g8[0], 2);
            g8[0] += __shfl_xor_sync(FULL, g8[0], 1);
            // lane owns S[(lane>>2)&7]; compute f once, broadcast f
            float S = g8[0];
            float f_own = S / ((1.f + S) * sqrtf(S + 1e-7f));
#pragma unroll
            for (int o = 0; o < 8; o++) {
                float f = __shfl_sync(FULL, f_own, (o << 2) | (lane & 3));
                act[o] = pre[o] * f;
            }
        }

        if (it < 2) {
            float g16[16];
            {
                bool up = (lane & 16) != 0;
#pragma unroll
                for (int k = 0; k < 16; k++) {
                    int i = k >> 3, o = k & 7;
                    float pk  = v[i][o] * act[o];
                    float pk2 = v[i + 2][o] * act[o];
                    float send = up ? pk : pk2;
                    float keep = up ? pk2 : pk;
                    g16[k] = keep + __shfl_xor_sync(FULL, send, 16);
                }
            }
            int len = 16;
#pragma unroll
            for (int m = 8; m >= 1; m >>= 1) {
                int half = len >> 1;
                bool up = (lane & m) != 0;
#pragma unroll
                for (int k = 0; k < 8; k++) {
                    if (k < half) {
                        float send = up ? g16[k] : g16[k + half];
                        float keep = up ? g16[k + half] : g16[k];
                        g16[k] = keep + __shfl_xor_sync(FULL, send, m);
                    }
                }
                len = half;
            }
            logit += g16[0];
        }
    }

    float* ob = out + ((b * 32 + lane) * 8) * 4096 + hw;
#pragma unroll
    for (int o = 0; o < 8; o++)
        ob[o * 4096] = act[o];
}

// ---------------------------------------------------------------------------
extern "C" void kernel_launch(void* const* d_in, const int* in_sizes, int n_in,
                              void* d_out, int out_size) {
    const float* x = (const float*)d_in[0];
    const float* W = (const float*)d_in[1];
    const float* b = (const float*)d_in[2];
    float* out = (float*)d_out;

    cudaFuncSetAttribute(conv_mma_kernel,
                         cudaFuncAttributeMaxDynamicSharedMemorySize, SMEM_BYTES);

    prep_t_kernel<<<2048, 256>>>(x);
    prep_wA_kernel<<<400, 256>>>(W);
    conv_mma_kernel<<<dim3(32, 2, 32), 256, SMEM_BYTES>>>();
    routing_kernel<<<4096, 256>>>(b, out);
}

// round 16
// speedup vs baseline: 1.1908x; 1.0255x over previous
#include <cuda_runtime.h>
#include <cuda_fp16.h>
#include <cstdint>

// ---------------------------------------------------------------------------
// Problem constants
//   x: (8, 16, 4, 64, 64) f32      A_IN=16, C_IN=4
//   W: (256, 16, 5, 5)    f32      C_OUT*A_OUT=256
//   b: (1, 1, 8, 32)      f32
//   out: (8, 32, 8, 64, 64) f32
// ---------------------------------------------------------------------------

static __device__ float g_t[32 * 16 * 64 * 64];      // conv input "t" (8 MB)
static __device__ __half g_wA[25 * 256 * 16];        // [pos][o][ic-permuted] fp16
static __device__ float g_conv[32 * 256 * 64 * 64];  // votes fp32 (134 MB)

// ---------------- PTX helpers ----------------------------------------------
__device__ __forceinline__ uint32_t smem_u32(const void* p) {
    uint32_t a;
    asm("{ .reg .u64 t; cvta.to.shared.u64 t, %1; cvt.u32.u64 %0, t; }"
        : "=r"(a) : "l"(p));
    return a;
}
__device__ __forceinline__ void ldm_x4(uint32_t* r, uint32_t addr) {
    asm volatile("ldmatrix.sync.aligned.m8n8.x4.shared.b16 {%0,%1,%2,%3}, [%4];"
                 : "=r"(r[0]), "=r"(r[1]), "=r"(r[2]), "=r"(r[3]) : "r"(addr));
}
__device__ __forceinline__ void mma_fp16(float* c, const uint32_t* a,
                                         uint32_t b0, uint32_t b1) {
    asm volatile(
        "mma.sync.aligned.m16n8k16.row.col.f32.f16.f16.f32 "
        "{%0,%1,%2,%3}, {%4,%5,%6,%7}, {%8,%9}, {%0,%1,%2,%3};"
        : "+f"(c[0]), "+f"(c[1]), "+f"(c[2]), "+f"(c[3])
        : "r"(a[0]), "r"(a[1]), "r"(a[2]), "r"(a[3]), "r"(b0), "r"(b1));
}

// smem: B halo only, 408 rows x 48B pitch (validated conflict-free)
#define B_OFF 0
#define SMEM_BYTES 20480   // 408*48 = 19584, rounded

// ---------------------------------------------------------------------------
// merged prep: blocks [0,2048) build g_t (smem transpose, validated R9);
// blocks [2048,2448) split weights to fp16 with LDG.64-fragment permutation
// (validated R11).
// ---------------------------------------------------------------------------
__global__ __launch_bounds__(256) void prep_kernel(const float* __restrict__ x,
                                                   const float* __restrict__ W) {
    const int tid = threadIdx.x;
    if (blockIdx.x < 2048) {
        __shared__ float s[16][65];
        const int blk = blockIdx.x;
        const int h  = blk & 63;
        const int ci = (blk >> 6) & 3;
        const int b  = blk >> 8;
        {
            const int a = tid >> 4, wq = (tid & 15) * 4;
            const float4 v = *(const float4*)(x + (((b * 16 + a) * 4 + ci) << 12)
                                                + (h << 6) + wq);
            s[a][wq]     = v.x;
            s[a][wq + 1] = v.y;
            s[a][wq + 2] = v.z;
            s[a][wq + 3] = v.w;
        }
        __syncthreads();
        {
            float* dst = g_t + (((ci * 8 + b) * 64 + h) << 6) * 16 + tid * 4;
            const int i0 = tid * 4;
            float4 v;
            v.x = s[(i0)     & 15][(i0)     >> 4];
            v.y = s[(i0 + 1) & 15][(i0 + 1) >> 4];
            v.z = s[(i0 + 2) & 15][(i0 + 2) >> 4];
            v.w = s[(i0 + 3) & 15][(i0 + 3) >> 4];
            *(float4*)dst = v;
        }
    } else {
        int idx = (blockIdx.x - 2048) * 256 + tid;   // 0..102399
        int ic  = idx & 15;
        int o   = (idx >> 4) & 255;
        int pos = idx >> 12;
        float w = W[o * 400 + ic * 25 + pos];
        int p  = ic >> 1;
        int sp = (p < 4) ? (2 * p) : (2 * (p - 4) + 1);
        int store_ic = sp * 2 + (ic & 1);
        g_wA[pos * 4096 + o * 16 + store_ic] = __float2half_rn(w);
    }
}

// ---------------------------------------------------------------------------
// conv: byte-identical to R15 (25 shifted GEMMs, single-pass fp16, fully
// unrolled with register double-buffered A prefetch).
// ---------------------------------------------------------------------------
__global__ __launch_bounds__(256, 2) void conv_mma_kernel() {
    extern __shared__ char dsm[];
    const int pxt = blockIdx.x;
    const int oh  = blockIdx.y;
    const int n   = blockIdx.z;
    const int tid = threadIdx.x;
    const int lane = tid & 31, wid = tid >> 5;
    const int wr = wid >> 2, wc = wid & 3;
    const int lh = wc >> 1, wwbase = (wc & 1) * 32;

    const uint32_t sb = smem_u32(dsm);
    const int hbase = pxt * 2;

    const int bRow = (lane & 7) + (lane >> 4) * 8;
    const int bCol = ((lane >> 3) & 1) * 8;
    const uint32_t bStat = (uint32_t)(bRow * 48 + bCol * 2);

    {
        const float* tn = g_t + n * 65536;
#pragma unroll
        for (int base = tid; base < 408; base += 256) {
            int r = base / 68, c = base % 68;
            int y = hbase + r - 2;
            int x = c - 2;
            bool ok = ((unsigned)y < 64u) && ((unsigned)x < 64u);
            __half* row = (__half*)(dsm + B_OFF + base * 48);
            const float* src = tn + y * 64 + x;
#pragma unroll
            for (int ic = 0; ic < 16; ic++) {
                float v = ok ? __ldg(src + ic * 4096) : 0.f;
                row[ic] = __float2half_rn(v);
            }
        }
    }
    __syncthreads();

    const uint2* gA2 = (const uint2*)g_wA;
    const int aBase = (oh * 128 + wr * 64 + (lane >> 2)) * 4 + (lane & 3);

    float acc[4][4][4];
#pragma unroll
    for (int mf = 0; mf < 4; mf++)
#pragma unroll
        for (int nf = 0; nf < 4; nf++)
#pragma unroll
            for (int q = 0; q < 4; q++) acc[mf][nf][q] = 0.f;

    uint2 nlo[4], nhi[4];
#pragma unroll
    for (int mf = 0; mf < 4; mf++) {
        nlo[mf] = __ldg(gA2 + aBase + mf * 64);
        nhi[mf] = __ldg(gA2 + aBase + mf * 64 + 32);
    }

#pragma unroll
    for (int pos = 0; pos < 25; pos++) {
        const int kh = pos / 5, kw = pos - kh * 5;

        uint32_t a4[4][4];
#pragma unroll
        for (int mf = 0; mf < 4; mf++) {
            a4[mf][0] = nlo[mf].x;
            a4[mf][2] = nlo[mf].y;
            a4[mf][1] = nhi[mf].x;
            a4[mf][3] = nhi[mf].y;
        }

        if (pos < 24) {
            const uint2* ap = gA2 + (pos + 1) * 1024 + aBase;
#pragma unroll
            for (int mf = 0; mf < 4; mf++) {
                nlo[mf] = __ldg(ap + mf * 64);
                nhi[mf] = __ldg(ap + mf * 64 + 32);
            }
        }

        const uint32_t Bb = sb + B_OFF
            + (uint32_t)(((lh + kh) * 68 + wwbase + kw) * 48) + bStat;
        uint32_t bh[2][4];
        ldm_x4(bh[0], Bb);
        ldm_x4(bh[1], Bb + 16 * 48);

#pragma unroll
        for (int mf = 0; mf < 4; mf++) {
            mma_fp16(acc[mf][0], a4[mf], bh[0][0], bh[0][1]);
            mma_fp16(acc[mf][1], a4[mf], bh[0][2], bh[0][3]);
            mma_fp16(acc[mf][2], a4[mf], bh[1][0], bh[1][1]);
            mma_fp16(acc[mf][3], a4[mf], bh[1][2], bh[1][3]);
        }
    }

    const int g2  = lane >> 2, t4 = lane & 3;
    float* outn = g_conv + n * 1048576;
    const int obase  = oh * 128 + wr * 64 + g2;
    const int pxbase = pxt * 128 + wc * 32 + 2 * t4;
#pragma unroll
    for (int mf = 0; mf < 4; mf++) {
#pragma unroll
        for (int nf = 0; nf < 4; nf++) {
            float* p0 = outn + (obase + mf * 16) * 4096 + pxbase + nf * 8;
            *(float2*)p0 = make_float2(acc[mf][nf][0], acc[mf][nf][1]);
            *(float2*)(p0 + 8 * 4096) = make_float2(acc[mf][nf][2], acc[mf][nf][3]);
        }
    }
}

// ---------------------------------------------------------------------------
// routing: one warp per pixel, lane = atom. R15 form + deferred squash scale:
// iters 0-1 reduce v*pre and scale the reduced agreement by f once (1 shfl)
// instead of broadcasting f 8-wide and scaling 32 products. Final iter
// materializes act for output.
// ---------------------------------------------------------------------------
__global__ __launch_bounds__(256, 4) void routing_kernel(const float* __restrict__ bias,
                                                         float* __restrict__ out) {
    const unsigned FULL = 0xffffffffu;
    __shared__ float s_bias[256];
    s_bias[threadIdx.x] = bias[threadIdx.x];
    __syncthreads();

    int gwarp = (blockIdx.x * 256 + threadIdx.x) >> 5;
    int lane  = threadIdx.x & 31;
    int b  = gwarp >> 12;
    int hw = gwarp & 4095;

    const float* vb = g_conv + b * 4194304 + hw * 256 + lane;
    float v[4][8];
#pragma unroll
    for (int i = 0; i < 4; i++)
#pragma unroll
        for (int o = 0; o < 8; o++)
            v[i][o] = __ldg(vb + i * 1048576 + o * 32);

    float logit = 0.f;
    float act[8];

#pragma unroll
    for (int it = 0; it < 3; it++) {
        float pre[8];
        if (it == 0) {
#pragma unroll
            for (int o = 0; o < 8; o++) {
                float p = s_bias[o * 32 + lane];
#pragma unroll
                for (int i = 0; i < 4; i++) p = fmaf(0.125f, v[i][o], p);
                pre[o] = p;
            }
        } else {
            float m = logit;
            m = fmaxf(m, __shfl_xor_sync(FULL, m, 1));
            m = fmaxf(m, __shfl_xor_sync(FULL, m, 2));
            m = fmaxf(m, __shfl_xor_sync(FULL, m, 4));
            float e = __expf(logit - m);
            float ssum = e;
            ssum += __shfl_xor_sync(FULL, ssum, 1);
            ssum += __shfl_xor_sync(FULL, ssum, 2);
            ssum += __shfl_xor_sync(FULL, ssum, 4);
            float route = e / ssum;
#pragma unroll
            for (int o = 0; o < 8; o++) {
                float p = s_bias[o * 32 + lane];
#pragma unroll
                for (int i = 0; i < 4; i++) {
                    float r = __shfl_sync(FULL, route, i * 8 + o);
                    p = fmaf(r, v[i][o], p);
                }
                pre[o] = p;
            }
        }

        // squash scale: S[o] reduction (transpose-reduce) -> f on owner lane
        float f_own;
        {
            float g8[8];
#pragma unroll
            for (int o = 0; o < 8; o++) g8[o] = pre[o] * pre[o];
            {
                bool up = (lane & 16) != 0;
#pragma unroll
                for (int k = 0; k < 4; k++) {
                    float send = up ? g8[k] : g8[k + 4];
                    float keep = up ? g8[k + 4] : g8[k];
                    g8[k] = keep + __shfl_xor_sync(FULL, send, 16);
                }
            }
            {
                bool up = (lane & 8) != 0;
#pragma unroll
                for (int k = 0; k < 2; k++) {
                    float send = up ? g8[k] : g8[k + 2];
                    float keep = up ? g8[k + 2] : g8[k];
                    g8[k] = keep + __shfl_xor_sync(FULL, send, 8);
                }
            }
            {
                bool up = (lane & 4) != 0;
                float send = up ? g8[0] : g8[1];
                float keep = up ? g8[1] : g8[0];
                g8[0] = keep + __shfl_xor_sync(FULL, send, 4);
            }
            g8[0] += __shfl_xor_sync(FULL, g8[0], 2);
            g8[0] += __shfl_xor_sync(FULL, g8[0], 1);
            float S = g8[0];                     // lane owns S[(lane>>2)&7]
            f_own = S / ((1.f + S) * sqrtf(S + 1e-7f));
        }

        if (it < 2) {
            // agreement on v*pre; scale by f AFTER the reduction (1 shfl)
            float g16[16];
            {
                bool up = (lane & 16) != 0;
#pragma unroll
                for (int k = 0; k < 16; k++) {
                    int i = k >> 3, o = k & 7;
                    float pk  = v[i][o] * pre[o];
                    float pk2 = v[i + 2][o] * pre[o];
                    float send = up ? pk : pk2;
                    float keep = up ? pk2 : pk;
                    g16[k] = keep + __shfl_xor_sync(FULL, send, 16);
                }
            }
            int len = 16;
#pragma unroll
            for (int m = 8; m >= 1; m >>= 1) {
                int half = len >> 1;
                bool up = (lane & m) != 0;
#pragma unroll
                for (int k = 0; k < 8; k++) {
                    if (k < half) {
                        float send = up ? g16[k] : g16[k + half];
                        float keep = up ? g16[k + half] : g16[k];
                        g16[k] = keep + __shfl_xor_sync(FULL, send, m);
                    }
                }
                len = half;
            }
            // lane owns agreement for (i = lane>>3, o = lane&7); needs f[o]
            float f_my = __shfl_sync(FULL, f_own, ((lane & 7) << 2) | (lane & 3));
            logit = fmaf(g16[0], f_my, logit);
        } else {
            // final iter: materialize act for output
#pragma unroll
            for (int o = 0; o < 8; o++) {
                float f = __shfl_sync(FULL, f_own, (o << 2) | (lane & 3));
                act[o] = pre[o] * f;
            }
        }
    }

    float* ob = out + ((b * 32 + lane) * 8) * 4096 + hw;
#pragma unroll
    for (int o = 0; o < 8; o++)
        ob[o * 4096] = act[o];
}

// ---------------------------------------------------------------------------
extern "C" void kernel_launch(void* const* d_in, const int* in_sizes, int n_in,
                              void* d_out, int out_size) {
    const float* x = (const float*)d_in[0];
    const float* W = (const float*)d_in[1];
    const float* b = (const float*)d_in[2];
    float* out = (float*)d_out;

    cudaFuncSetAttribute(conv_mma_kernel,
                         cudaFuncAttributeMaxDynamicSharedMemorySize, SMEM_BYTES);

    prep_kernel<<<2448, 256>>>(x, W);
    conv_mma_kernel<<<dim3(32, 2, 32), 256, SMEM_BYTES>>>();
    routing_kernel<<<4096, 256>>>(b, out);
}

// round 17
// speedup vs baseline: 1.3295x; 1.1165x over previous
#include <cuda_runtime.h>
#include <cuda_fp16.h>
#include <cstdint>

// ---------------------------------------------------------------------------
// Problem constants
//   x: (8, 16, 4, 64, 64) f32      A_IN=16, C_IN=4
//   W: (256, 16, 5, 5)    f32      C_OUT*A_OUT=256
//   b: (1, 1, 8, 32)      f32
//   out: (8, 32, 8, 64, 64) f32
// ---------------------------------------------------------------------------

static __device__ float g_t[32 * 16 * 64 * 64];      // conv input "t" (8 MB)
static __device__ __half g_wA[25 * 256 * 16];        // [pos][o][ic-permuted] fp16
static __device__ float g_conv[32 * 256 * 64 * 64];  // votes fp32 (134 MB)

// ---------------- PTX helpers ----------------------------------------------
__device__ __forceinline__ uint32_t smem_u32(const void* p) {
    uint32_t a;
    asm("{ .reg .u64 t; cvta.to.shared.u64 t, %1; cvt.u32.u64 %0, t; }"
        : "=r"(a) : "l"(p));
    return a;
}
__device__ __forceinline__ void ldm_x4(uint32_t* r, uint32_t addr) {
    asm volatile("ldmatrix.sync.aligned.m8n8.x4.shared.b16 {%0,%1,%2,%3}, [%4];"
                 : "=r"(r[0]), "=r"(r[1]), "=r"(r[2]), "=r"(r[3]) : "r"(addr));
}
__device__ __forceinline__ void mma_fp16(float* c, const uint32_t* a,
                                         uint32_t b0, uint32_t b1) {
    asm volatile(
        "mma.sync.aligned.m16n8k16.row.col.f32.f16.f16.f32 "
        "{%0,%1,%2,%3}, {%4,%5,%6,%7}, {%8,%9}, {%0,%1,%2,%3};"
        : "+f"(c[0]), "+f"(c[1]), "+f"(c[2]), "+f"(c[3])
        : "r"(a[0]), "r"(a[1]), "r"(a[2]), "r"(a[3]), "r"(b0), "r"(b1));
}

// smem: B halo only, 408 rows x 48B pitch (validated conflict-free)
#define B_OFF 0
#define SMEM_BYTES 20480   // 408*48 = 19584, rounded

// ---------------------------------------------------------------------------
// merged prep: blocks [0,2048) build g_t (smem transpose, validated R9);
// blocks [2048,2448) split weights to fp16 with LDG.64-fragment permutation
// (validated R11).
// ---------------------------------------------------------------------------
__global__ __launch_bounds__(256) void prep_kernel(const float* __restrict__ x,
                                                   const float* __restrict__ W) {
    const int tid = threadIdx.x;
    if (blockIdx.x < 2048) {
        __shared__ float s[16][65];
        const int blk = blockIdx.x;
        const int h  = blk & 63;
        const int ci = (blk >> 6) & 3;
        const int b  = blk >> 8;
        {
            const int a = tid >> 4, wq = (tid & 15) * 4;
            const float4 v = *(const float4*)(x + (((b * 16 + a) * 4 + ci) << 12)
                                                + (h << 6) + wq);
            s[a][wq]     = v.x;
            s[a][wq + 1] = v.y;
            s[a][wq + 2] = v.z;
            s[a][wq + 3] = v.w;
        }
        __syncthreads();
        {
            float* dst = g_t + (((ci * 8 + b) * 64 + h) << 6) * 16 + tid * 4;
            const int i0 = tid * 4;
            float4 v;
            v.x = s[(i0)     & 15][(i0)     >> 4];
            v.y = s[(i0 + 1) & 15][(i0 + 1) >> 4];
            v.z = s[(i0 + 2) & 15][(i0 + 2) >> 4];
            v.w = s[(i0 + 3) & 15][(i0 + 3) >> 4];
            *(float4*)dst = v;
        }
    } else {
        int idx = (blockIdx.x - 2048) * 256 + tid;   // 0..102399
        int ic  = idx & 15;
        int o   = (idx >> 4) & 255;
        int pos = idx >> 12;
        float w = W[o * 400 + ic * 25 + pos];
        int p  = ic >> 1;
        int sp = (p < 4) ? (2 * p) : (2 * (p - 4) + 1);
        int store_ic = sp * 2 + (ic & 1);
        g_wA[pos * 4096 + o * 16 + store_ic] = __float2half_rn(w);
    }
}

// ---------------------------------------------------------------------------
// conv: byte-identical to R15/R16 (25 shifted GEMMs, single-pass fp16, fully
// unrolled with register double-buffered A prefetch).
// ---------------------------------------------------------------------------
__global__ __launch_bounds__(256, 2) void conv_mma_kernel() {
    extern __shared__ char dsm[];
    const int pxt = blockIdx.x;
    const int oh  = blockIdx.y;
    const int n   = blockIdx.z;
    const int tid = threadIdx.x;
    const int lane = tid & 31, wid = tid >> 5;
    const int wr = wid >> 2, wc = wid & 3;
    const int lh = wc >> 1, wwbase = (wc & 1) * 32;

    const uint32_t sb = smem_u32(dsm);
    const int hbase = pxt * 2;

    const int bRow = (lane & 7) + (lane >> 4) * 8;
    const int bCol = ((lane >> 3) & 1) * 8;
    const uint32_t bStat = (uint32_t)(bRow * 48 + bCol * 2);

    {
        const float* tn = g_t + n * 65536;
#pragma unroll
        for (int base = tid; base < 408; base += 256) {
            int r = base / 68, c = base % 68;
            int y = hbase + r - 2;
            int x = c - 2;
            bool ok = ((unsigned)y < 64u) && ((unsigned)x < 64u);
            __half* row = (__half*)(dsm + B_OFF + base * 48);
            const float* src = tn + y * 64 + x;
#pragma unroll
            for (int ic = 0; ic < 16; ic++) {
                float v = ok ? __ldg(src + ic * 4096) : 0.f;
                row[ic] = __float2half_rn(v);
            }
        }
    }
    __syncthreads();

    const uint2* gA2 = (const uint2*)g_wA;
    const int aBase = (oh * 128 + wr * 64 + (lane >> 2)) * 4 + (lane & 3);

    float acc[4][4][4];
#pragma unroll
    for (int mf = 0; mf < 4; mf++)
#pragma unroll
        for (int nf = 0; nf < 4; nf++)
#pragma unroll
            for (int q = 0; q < 4; q++) acc[mf][nf][q] = 0.f;

    uint2 nlo[4], nhi[4];
#pragma unroll
    for (int mf = 0; mf < 4; mf++) {
        nlo[mf] = __ldg(gA2 + aBase + mf * 64);
        nhi[mf] = __ldg(gA2 + aBase + mf * 64 + 32);
    }

#pragma unroll
    for (int pos = 0; pos < 25; pos++) {
        const int kh = pos / 5, kw = pos - kh * 5;

        uint32_t a4[4][4];
#pragma unroll
        for (int mf = 0; mf < 4; mf++) {
            a4[mf][0] = nlo[mf].x;
            a4[mf][2] = nlo[mf].y;
            a4[mf][1] = nhi[mf].x;
            a4[mf][3] = nhi[mf].y;
        }

        if (pos < 24) {
            const uint2* ap = gA2 + (pos + 1) * 1024 + aBase;
#pragma unroll
            for (int mf = 0; mf < 4; mf++) {
                nlo[mf] = __ldg(ap + mf * 64);
                nhi[mf] = __ldg(ap + mf * 64 + 32);
            }
        }

        const uint32_t Bb = sb + B_OFF
            + (uint32_t)(((lh + kh) * 68 + wwbase + kw) * 48) + bStat;
        uint32_t bh[2][4];
        ldm_x4(bh[0], Bb);
        ldm_x4(bh[1], Bb + 16 * 48);

#pragma unroll
        for (int mf = 0; mf < 4; mf++) {
            mma_fp16(acc[mf][0], a4[mf], bh[0][0], bh[0][1]);
            mma_fp16(acc[mf][1], a4[mf], bh[0][2], bh[0][3]);
            mma_fp16(acc[mf][2], a4[mf], bh[1][0], bh[1][1]);
            mma_fp16(acc[mf][3], a4[mf], bh[1][2], bh[1][3]);
        }
    }

    const int g2  = lane >> 2, t4 = lane & 3;
    float* outn = g_conv + n * 1048576;
    const int obase  = oh * 128 + wr * 64 + g2;
    const int pxbase = pxt * 128 + wc * 32 + 2 * t4;
#pragma unroll
    for (int mf = 0; mf < 4; mf++) {
#pragma unroll
        for (int nf = 0; nf < 4; nf++) {
            float* p0 = outn + (obase + mf * 16) * 4096 + pxbase + nf * 8;
            *(float2*)p0 = make_float2(acc[mf][nf][0], acc[mf][nf][1]);
            *(float2*)(p0 + 8 * 4096) = make_float2(acc[mf][nf][2], acc[mf][nf][3]);
        }
    }
}

// ---------------------------------------------------------------------------
// routing: one warp per pixel, lane = atom. R16 math (deferred squash scale).
// NEW: output staged through smem and written coalesced — each thread owns
// one (a,o) pair and writes its block's 8 consecutive hw as 2x STG.128
// (full 32B sectors) instead of 8 scattered STG.32 (256 sectors/warp).
// ---------------------------------------------------------------------------
__global__ __launch_bounds__(256, 4) void routing_kernel(const float* __restrict__ bias,
                                                         float* __restrict__ out) {
    const unsigned FULL = 0xffffffffu;
    __shared__ float s_bias[256];
    __shared__ float s_act[32 * 65];     // [a]*65 + o*8 + w  (pitch 65: no conflicts)
    s_bias[threadIdx.x] = bias[threadIdx.x];
    __syncthreads();

    int gwarp = (blockIdx.x * 256 + threadIdx.x) >> 5;
    int lane  = threadIdx.x & 31;
    int wloc  = (threadIdx.x >> 5) & 7;
    int b  = gwarp >> 12;
    int hw = gwarp & 4095;

    const float* vb = g_conv + b * 4194304 + hw * 256 + lane;
    float v[4][8];
#pragma unroll
    for (int i = 0; i < 4; i++)
#pragma unroll
        for (int o = 0; o < 8; o++)
            v[i][o] = __ldg(vb + i * 1048576 + o * 32);

    float logit = 0.f;
    float act[8];

#pragma unroll
    for (int it = 0; it < 3; it++) {
        float pre[8];
        if (it == 0) {
#pragma unroll
            for (int o = 0; o < 8; o++) {
                float p = s_bias[o * 32 + lane];
#pragma unroll
                for (int i = 0; i < 4; i++) p = fmaf(0.125f, v[i][o], p);
                pre[o] = p;
            }
        } else {
            float m = logit;
            m = fmaxf(m, __shfl_xor_sync(FULL, m, 1));
            m = fmaxf(m, __shfl_xor_sync(FULL, m, 2));
            m = fmaxf(m, __shfl_xor_sync(FULL, m, 4));
            float e = __expf(logit - m);
            float ssum = e;
            ssum += __shfl_xor_sync(FULL, ssum, 1);
            ssum += __shfl_xor_sync(FULL, ssum, 2);
            ssum += __shfl_xor_sync(FULL, ssum, 4);
            float route = e / ssum;
#pragma unroll
            for (int o = 0; o < 8; o++) {
                float p = s_bias[o * 32 + lane];
#pragma unroll
                for (int i = 0; i < 4; i++) {
                    float r = __shfl_sync(FULL, route, i * 8 + o);
                    p = fmaf(r, v[i][o], p);
                }
                pre[o] = p;
            }
        }

        // squash scale: S[o] reduction (transpose-reduce) -> f on owner lane
        float f_own;
        {
            float g8[8];
#pragma unroll
            for (int o = 0; o < 8; o++) g8[o] = pre[o] * pre[o];
            {
                bool up = (lane & 16) != 0;
#pragma unroll
                for (int k = 0; k < 4; k++) {
                    float send = up ? g8[k] : g8[k + 4];
                    float keep = up ? g8[k + 4] : g8[k];
                    g8[k] = keep + __shfl_xor_sync(FULL, send, 16);
                }
            }
            {
                bool up = (lane & 8) != 0;
#pragma unroll
                for (int k = 0; k < 2; k++) {
                    float send = up ? g8[k] : g8[k + 2];
                    float keep = up ? g8[k + 2] : g8[k];
                    g8[k] = keep + __shfl_xor_sync(FULL, send, 8);
                }
            }
            {
                bool up = (lane & 4) != 0;
                float send = up ? g8[0] : g8[1];
                float keep = up ? g8[1] : g8[0];
                g8[0] = keep + __shfl_xor_sync(FULL, send, 4);
            }
            g8[0] += __shfl_xor_sync(FULL, g8[0], 2);
            g8[0] += __shfl_xor_sync(FULL, g8[0], 1);
            float S = g8[0];                     // lane owns S[(lane>>2)&7]
            f_own = S / ((1.f + S) * sqrtf(S + 1e-7f));
        }

        if (it < 2) {
            // agreement on v*pre; scale by f AFTER the reduction (1 shfl)
            float g16[16];
            {
                bool up = (lane & 16) != 0;
#pragma unroll
                for (int k = 0; k < 16; k++) {
                    int i = k >> 3, o = k & 7;
                    float pk  = v[i][o] * pre[o];
                    float pk2 = v[i + 2][o] * pre[o];
                    float send = up ? pk : pk2;
                    float keep = up ? pk2 : pk;
                    g16[k] = keep + __shfl_xor_sync(FULL, send, 16);
                }
            }
            int len = 16;
#pragma unroll
            for (int m = 8; m >= 1; m >>= 1) {
                int half = len >> 1;
                bool up = (lane & m) != 0;
#pragma unroll
                for (int k = 0; k < 8; k++) {
                    if (k < half) {
                        float send = up ? g16[k] : g16[k + half];
                        float keep = up ? g16[k + half] : g16[k];
                        g16[k] = keep + __shfl_xor_sync(FULL, send, m);
                    }
                }
                len = half;
            }
            float f_my = __shfl_sync(FULL, f_own, ((lane & 7) << 2) | (lane & 3));
            logit = fmaf(g16[0], f_my, logit);
        } else {
#pragma unroll
            for (int o = 0; o < 8; o++) {
                float f = __shfl_sync(FULL, f_own, (o << 2) | (lane & 3));
                act[o] = pre[o] * f;
            }
        }
    }

    // ---- coalesced output: stage in smem, write 32B blocks per thread -----
#pragma unroll
    for (int o = 0; o < 8; o++)
        s_act[lane * 65 + o * 8 + wloc] = act[o];
    __syncthreads();
    {
        const int a2 = threadIdx.x >> 3;      // 0..31
        const int o2 = threadIdx.x & 7;       // 0..7
        const int hwbase = (blockIdx.x & 511) * 8;
        const int bb = blockIdx.x >> 9;
        float vals[8];
#pragma unroll
        for (int w = 0; w < 8; w++)
            vals[w] = s_act[a2 * 65 + o2 * 8 + w];
        float* op = out + ((bb * 32 + a2) * 8 + o2) * 4096 + hwbase;
        *(float4*)op       = make_float4(vals[0], vals[1], vals[2], vals[3]);
        *(float4*)(op + 4) = make_float4(vals[4], vals[5], vals[6], vals[7]);
    }
}

// ---------------------------------------------------------------------------
extern "C" void kernel_launch(void* const* d_in, const int* in_sizes, int n_in,
                              void* d_out, int out_size) {
    const float* x = (const float*)d_in[0];
    const float* W = (const float*)d_in[1];
    const float* b = (const float*)d_in[2];
    float* out = (float*)d_out;

    cudaFuncSetAttribute(conv_mma_kernel,
                         cudaFuncAttributeMaxDynamicSharedMemorySize, SMEM_BYTES);

    prep_kernel<<<2448, 256>>>(x, W);
    conv_mma_kernel<<<dim3(32, 2, 32), 256, SMEM_BYTES>>>();
    routing_kernel<<<4096, 256>>>(b, out);
}